// round 17
// baseline (speedup 1.0000x reference)
#include <cuda_runtime.h>
#include <stdint.h>

// Problem constants (from reference)
#define MASS_H2O   18.01056f
#define MASS_NH3   17.02655f
#define MAX_MZ     30000
#define WINDOW     10
#define VOCAB      26
#define BATCH      32768
#define IONS       8

#define TOTAL_GROUPS     (BATCH * VOCAB)               // 851,968
#define TILE_GROUPS      512
#define NUM_TILES        (TOTAL_GROUPS / TILE_GROUPS)  // 1664 exactly
#define WINDOWS_PER_TILE (TILE_GROUPS * IONS)          // 4096
#define ELEMS_PER_TILE   (WINDOWS_PER_TILE * WINDOW)   // 40960
#define VEC2_PER_TILE    (ELEMS_PER_TILE / 2)          // 20480
#define THREADS          1024
#define VEC2_PER_THREAD  (VEC2_PER_TILE / THREADS)     // 20
#define ABATCH           5                             // per-batch MLP depth

#define SPEC_FLOATS_PAD  30016                  // 30000 + 16 zero pad
#define SPEC_BYTES       (SPEC_FLOATS_PAD * 4)  // 120,064
#define METABUF          (WINDOWS_PER_TILE + 4)
#define META_BYTES       (4 * METABUF * 4)      // 4 buffers: 65,600
#define SMEM_BYTES       (SPEC_BYTES + META_BYTES)     // 185,664

#define ZERO_IDX    30000                       // points at zero pad
#define GRID_BLOCKS 152
#define PAIR_STRIDE (2 * GRID_BLOCKS)           // 304

// One ion-variant window base from c (already cb or cy). EXACT reference
// arithmetic: variant first (single rounding), then *10, round-half-even.
__device__ __forceinline__
int one_meta(float c, int jj, bool vok)
{
    float m;
    if      (jj == 1) m = c - MASS_H2O;
    else if (jj == 2) m = c - MASS_NH3;
    else if (jj == 3) m = c * 0.5f;
    else              m = c;
    const int  idx  = __float2int_rn(m * 10.0f) - (WINDOW / 2);
    const bool keep = (idx >= 0) && (idx <= MAX_MZ - WINDOW) && vok;
    return keep ? idx : ZERO_IDX;
}

// Publish this thread's 4 windows (one STS.128) from pre-loaded inputs.
__device__ __forceinline__
void publish(int* __restrict__ mb, int tid, float pm, float pf, float ms,
             int v, int half, int dir)
{
    float cb, cy;
    if (dir == 0) { cb = pf + ms; cy = pm - cb; }
    else          { cy = pf + ms; cb = pm - cy; }
    const float c   = half ? cy : cb;
    const bool  vok = (v >= 3);
    int4 mw;
    mw.x = one_meta(c, 0, vok);
    mw.y = one_meta(c, 1, vok);
    mw.z = one_meta(c, 2, vok);
    mw.w = one_meta(c, 3, vok);
    reinterpret_cast<int4*>(mb)[tid] = mw;       // windows 4*tid..4*tid+3
}

// R13's proven 3-stage phase 2 for one tile.
__device__ __forceinline__
void phase2(const int* __restrict__ mb, const float* __restrict__ spec,
            float* __restrict__ out, int tile, int tid)
{
    float2* out2 = reinterpret_cast<float2*>(out) + tile * VEC2_PER_TILE;

    #pragma unroll
    for (int kk = 0; kk < VEC2_PER_THREAD / ABATCH; ++kk) {
        const int q0 = tid + kk * ABATCH * THREADS;
        int addr[ABATCH];

        #pragma unroll
        for (int j = 0; j < ABATCH; ++j) {
            const int q = q0 + j * THREADS;
            const unsigned win = (unsigned)q / 5u;   // window = (2q)/10
            const int w0 = (q - (int)win * 5) * 2;   // in {0,2,4,6,8}
            addr[j] = mb[win] + w0;                  // LDS.32 meta burst
        }

        float2 val[ABATCH];
        #pragma unroll
        for (int j = 0; j < ABATCH; ++j) {
            val[j].x = spec[addr[j]];
            val[j].y = spec[addr[j] + 1];
        }

        #pragma unroll
        for (int j = 0; j < ABATCH; ++j)
            __stcs(out2 + q0 + j * THREADS, val[j]); // streaming STG.64
    }
}

__global__ void __launch_bounds__(THREADS, 1)
intensity_kernel(const float* __restrict__ pepmass,
                 const float* __restrict__ prefix_mass,
                 const float* __restrict__ masses,
                 const float* __restrict__ spectrum,
                 const int*   __restrict__ dir_ptr,
                 float* __restrict__ out)
{
    extern __shared__ unsigned char smem_raw[];
    float* spec = reinterpret_cast<float*>(smem_raw);
    int*   meta = reinterpret_cast<int*>(smem_raw + SPEC_BYTES);

    const int tid  = threadIdx.x;
    const int dir  = dir_ptr ? __ldg(dir_ptr) : 0;
    const int gl   = tid >> 1;          // group within tile owned by thread
    const int half = tid & 1;           // 0 -> ions 0..3 (cb), 1 -> ions 4..7 (cy)

    // ---- stage spectrum into SMEM (zero the 16-float pad) ----
    {
        const float4* s4 = reinterpret_cast<const float4*>(spectrum);
        float4*       d4 = reinterpret_cast<float4*>(spec);
        const float4  z4 = make_float4(0.f, 0.f, 0.f, 0.f);
        #pragma unroll 2
        for (int i = tid; i < SPEC_FLOATS_PAD / 4; i += THREADS)
            d4[i] = (i < MAX_MZ / 4) ? s4[i] : z4;
    }

    // ---- prologue: prefetch inputs for tiles (bid, bid+152) ----
    float pmA, pfA, msA, pmB, pfB, msB;
    int   vA, vB;
    {
        const int gA = blockIdx.x * TILE_GROUPS + gl;
        const int bA = gA / VOCAB;  vA = gA - bA * VOCAB;
        pmA = __ldg(pepmass + bA); pfA = __ldg(prefix_mass + bA); msA = __ldg(masses + vA);
        int tB = blockIdx.x + GRID_BLOCKS;
        if (tB >= NUM_TILES) tB = blockIdx.x;        // clamp (tiny grids only)
        const int gB = tB * TILE_GROUPS + gl;
        const int bB = gB / VOCAB;  vB = gB - bB * VOCAB;
        pmB = __ldg(pepmass + bB); pfB = __ldg(prefix_mass + bB); msB = __ldg(masses + vB);
    }

    int p = 0;
    for (int tile = blockIdx.x; tile < NUM_TILES; tile += PAIR_STRIDE) {
        const int  tB   = tile + GRID_BLOCKS;
        const bool hasB = (tB < NUM_TILES);          // block-uniform
        int* mbA = meta + (p * 2) * METABUF;
        int* mbB = mbA + METABUF;
        p ^= 1;

        // ---- publish both tiles' metadata ----
        publish(mbA, tid, pmA, pfA, msA, vA, half, dir);
        if (hasB)
            publish(mbB, tid, pmB, pfB, msB, vB, half, dir);

        // ---- prefetch NEXT pair's inputs BEFORE the barrier ----
        {
            int nA = tile + PAIR_STRIDE;
            if (nA >= NUM_TILES) nA = tile;          // clamp: harmless reload
            int nB = nA + GRID_BLOCKS;
            if (nB >= NUM_TILES) nB = nA;
            const int gA = nA * TILE_GROUPS + gl;
            const int bA = gA / VOCAB;  vA = gA - bA * VOCAB;
            pmA = __ldg(pepmass + bA); pfA = __ldg(prefix_mass + bA); msA = __ldg(masses + vA);
            const int gB = nB * TILE_GROUPS + gl;
            const int bB = gB / VOCAB;  vB = gB - bB * VOCAB;
            pmB = __ldg(pepmass + bB); pfB = __ldg(prefix_mass + bB); msB = __ldg(masses + vB);
        }

        __syncthreads();   // ONE barrier per two tiles
                           // (first iteration: also covers spectrum staging)

        // ---- phase 2 for both tiles ----
        phase2(mbA, spec, out, tile, tid);
        if (hasB)
            phase2(mbB, spec, out, tB, tid);
        // no trailing sync: 4 meta buffers alternate between iteration
        // parities; the barrier above proves all readers of the other
        // parity's buffers finished before they are rewritten.
    }
}

extern "C" void kernel_launch(void* const* d_in, const int* in_sizes, int n_in,
                              void* d_out, int out_size)
{
    const float* spectrum    = (const float*)d_in[0];
    const float* pepmass     = (const float*)d_in[1];
    const float* prefix_mass = (const float*)d_in[2];
    const float* masses      = (const float*)d_in[3];
    const int*   dir_ptr     = (n_in >= 5) ? (const int*)d_in[4] : nullptr;
    float*       out         = (float*)d_out;

    cudaFuncSetAttribute(intensity_kernel,
                         cudaFuncAttributeMaxDynamicSharedMemorySize, SMEM_BYTES);

    intensity_kernel<<<GRID_BLOCKS, THREADS, SMEM_BYTES>>>(
        pepmass, prefix_mass, masses, spectrum, dir_ptr, out);
}